// round 15
// baseline (speedup 1.0000x reference)
#include <cuda_runtime.h>
#include <cuda_fp16.h>
#include <math.h>
#include <stdint.h>

#define B_ 4
#define T_ 2048
#define E_ 1024
#define H_ 16

// Device-global scratch (allocation-free).
__device__ __half   g_Xh[(size_t)3 * B_ * T_ * E_];
__device__ __half   g_Wph[(size_t)E_ * E_];
__device__ __half   g_Wth[(size_t)3 * E_ * E_];
__device__ uint32_t g_Qfh[(size_t)64 * 16 * 4096];
__device__ uint32_t g_Kfh[(size_t)64 * 32 * 2048];
__device__ uint32_t g_Vfh[(size_t)64 * 32 * 2048];
__device__ __half   g_attnh[(size_t)B_ * T_ * E_];

// ============================================================================
// Helpers
// ============================================================================
__device__ __forceinline__ uint32_t packh2(float lo, float hi) {
    uint32_t r;
    asm("cvt.rn.f16x2.f32 %0, %1, %2;" : "=r"(r) : "f"(hi), "f"(lo));
    return r;
}

__device__ __forceinline__ float ex2f(float x) {
    float y;
    asm("ex2.approx.f32 %0, %1;" : "=f"(y) : "f"(x));
    return y;
}

// two fp16 exp2 in ONE MUFU op
__device__ __forceinline__ uint32_t ex2h2(uint32_t x) {
    uint32_t y;
    asm("ex2.approx.f16x2 %0, %1;" : "=r"(y) : "r"(x));
    return y;
}

__device__ __forceinline__ uint32_t smem_u32(const void* p) {
    uint32_t a;
    asm("{ .reg .u64 t; cvta.to.shared.u64 t, %1; cvt.u32.u64 %0, t; }"
        : "=r"(a) : "l"(p));
    return a;
}

// D(16x8,f32) += A(16x16,f16) * B(16x8,f16)
__device__ __forceinline__ void mma16h(float* c, const uint32_t* a, const uint32_t* b) {
    asm volatile(
        "mma.sync.aligned.m16n8k16.row.col.f32.f16.f16.f32 "
        "{%0,%1,%2,%3}, {%4,%5,%6,%7}, {%8,%9}, {%0,%1,%2,%3};"
        : "+f"(c[0]), "+f"(c[1]), "+f"(c[2]), "+f"(c[3])
        : "r"(a[0]), "r"(a[1]), "r"(a[2]), "r"(a[3]), "r"(b[0]), "r"(b[1]));
}

__device__ __forceinline__ void ldsm4(uint32_t* r, uint32_t a) {
    asm volatile("ldmatrix.sync.aligned.m8n8.x4.shared.b16 {%0,%1,%2,%3}, [%4];"
                 : "=r"(r[0]), "=r"(r[1]), "=r"(r[2]), "=r"(r[3]) : "r"(a));
}

__device__ __forceinline__ void cp16(uint32_t dst, const void* src) {
    asm volatile("cp.async.cg.shared.global [%0], [%1], 16;"
                 :: "r"(dst), "l"(src));
}
#define CP_COMMIT asm volatile("cp.async.commit_group;" ::: "memory")
#define CP_WAIT0  asm volatile("cp.async.wait_group 0;" ::: "memory")
#define CP_WAIT1  asm volatile("cp.async.wait_group 1;" ::: "memory")

// ============================================================================
// Merged prologue: z=0..3 -> g_Xh[z]=fp16(q|k|v), g_Wph=fp16(Wp);
//                  z=4    -> transpose all three W's into g_Wth.
// grid (8192, 5), 256 threads.
// ============================================================================
__global__ __launch_bounds__(256) void prologue_kernel(
    const float* __restrict__ q, const float* __restrict__ k,
    const float* __restrict__ v, const float* __restrict__ Wp,
    const float* __restrict__ Wq, const float* __restrict__ Wk,
    const float* __restrict__ Wv)
{
    const int z = blockIdx.y;
    const int tid = threadIdx.x;

    if (z < 4) {
        const float* src;
        __half* dst;
        size_t n4;
        if (z < 3) {
            src = (z == 0 ? q : (z == 1 ? k : v));
            dst = g_Xh + (size_t)z * B_ * T_ * E_;
            n4  = (size_t)B_ * T_ * E_ / 4;
        } else {
            src = Wp;
            dst = g_Wph;
            n4  = (size_t)E_ * E_ / 4;
        }
        size_t i = (size_t)blockIdx.x * 256 + tid;
        if (i < n4) {
            float4 x = ((const float4*)src)[i];
            uint2 o;
            o.x = packh2(x.x, x.y);
            o.y = packh2(x.z, x.w);
            ((uint2*)dst)[i] = o;
        }
        return;
    }

    // z == 4: weight transpose. 768 active blocks.
    if (blockIdx.x >= 768) return;
    __shared__ float tile[64][65];
    const int which = blockIdx.x >> 8;          // 0..2
    const int rem   = blockIdx.x & 255;
    const int h     = rem >> 4;                 // 0..15
    const int e0    = (rem & 15) * 64;
    const float* W = (which == 0 ? Wq : (which == 1 ? Wk : Wv)) + (size_t)h * E_ * 64;

#pragma unroll
    for (int u = 0; u < 16; u++) {
        int idx = tid + u * 256;
        int r = idx >> 6, c = idx & 63;
        tile[r][c] = W[(size_t)(e0 + r) * 64 + c];
    }
    __syncthreads();

    __half* out = g_Wth + (size_t)which * E_ * E_;
#pragma unroll
    for (int u = 0; u < 16; u++) {
        int idx = tid + u * 256;
        int d = idx >> 6, ee = idx & 63;
        out[(size_t)(h * 64 + d) * E_ + e0 + ee] = __float2half_rn(tile[ee][d]);
    }
}

// ============================================================================
// fp16 GEMM core (cp.async 3-stage, ldmatrix, BK=64) — R10 config:
// C[128,128] = A[128,K=1024] @ B[128,K=1024]^T, 16 chunks of 64 (4 k16 steps).
// 256 threads / 8 warps (4M x 2N), warp tile 32x64. smem row 72 halves
// (stride-36 words: 8 rows x stride-36 -> phases 4r mod 32 distinct, LDSM cf).
// ============================================================================
#define HLD 36
#define GSW (128 * HLD)
#define GEMM_SMEM_BYTES (6 * GSW * 4)        // 110592

__device__ __forceinline__ void gemm_issue_h(
    const __half* __restrict__ A, const __half* __restrict__ Bm,
    uint32_t su, int c, int s, int tid)
{
    const __half* Ac = A + (c << 6);
    const __half* Bc = Bm + (c << 6);
    const uint32_t ab = su + (uint32_t)s * GSW * 4;
    const uint32_t bb = su + (uint32_t)(3 + s) * GSW * 4;
#pragma unroll
    for (int u = 0; u < 4; u++) {
        int idx = tid + (u << 8);           // 0..1023
        int r = idx >> 3, qq = idx & 7;
        uint32_t so = (uint32_t)r * 144 + (uint32_t)qq * 16;
        cp16(ab + so, Ac + (size_t)r * E_ + (qq << 3));
        cp16(bb + so, Bc + (size_t)r * E_ + (qq << 3));
    }
    CP_COMMIT;
}

__device__ __forceinline__ void gemm_tile_h(
    const __half* __restrict__ A, const __half* __restrict__ Bm,
    uint32_t* smw, float C[2][8][4])
{
    const int tid = threadIdx.x, wid = tid >> 5, lane = tid & 31;
    const int mw = (wid & 3) * 32, nw = (wid >> 2) * 64;
    const int i0 = lane & 7, sel = lane >> 3;
    const uint32_t su = smem_u32(smw);

    const int arow = (mw + i0 + ((sel & 1) << 3)) * HLD + ((sel >> 1) << 2);
    int brow[4];
#pragma unroll
    for (int p = 0; p < 4; p++)
        brow[p] = (nw + 16 * p + ((sel >> 1) << 3) + i0) * HLD + ((sel & 1) << 2);

#pragma unroll
    for (int i = 0; i < 2; i++)
#pragma unroll
        for (int j = 0; j < 8; j++)
#pragma unroll
            for (int p = 0; p < 4; p++) C[i][j][p] = 0.f;

    gemm_issue_h(A, Bm, su, 0, 0, tid);
    gemm_issue_h(A, Bm, su, 1, 1, tid);

    int s = 0;
    for (int c = 0; c < 16; c++) {
        if (c < 15) { CP_WAIT1; } else { CP_WAIT0; }
        __syncthreads();
        if (c + 2 < 16) {
            int sn = s + 2; if (sn >= 3) sn -= 3;
            gemm_issue_h(A, Bm, su, c + 2, sn, tid);
        }
        const uint32_t aBase = su + (uint32_t)s * (GSW * 4);
        const uint32_t bBase = su + (uint32_t)(3 + s) * (GSW * 4);
#pragma unroll
        for (int ks = 0; ks < 4; ks++) {
            const int ko = ks * 8;
            uint32_t af[2][4], bf[4][4];
            ldsm4(af[0], aBase + (uint32_t)(arow + ko) * 4);
            ldsm4(af[1], aBase + (uint32_t)(arow + 16 * HLD + ko) * 4);
#pragma unroll
            for (int p = 0; p < 4; p++)
                ldsm4(bf[p], bBase + (uint32_t)(brow[p] + ko) * 4);
#pragma unroll
            for (int i = 0; i < 2; i++)
#pragma unroll
                for (int p = 0; p < 4; p++) {
                    mma16h(C[i][2 * p],     af[i], &bf[p][0]);
                    mma16h(C[i][2 * p + 1], af[i], &bf[p][2]);
                }
        }
        if (++s == 3) s = 0;
    }
}

// ============================================================================
// QKV projection: grid (T/128, E/128, 12 = which*4+b). 256 threads.
// Epilogue packs fp16x2 and scatters into fragment blobs. Q stays UNscaled.
// ============================================================================
__global__ __launch_bounds__(256, 2) void proj_mma_kernel()
{
    extern __shared__ uint32_t gsm[];
    const int which = blockIdx.z >> 2;
    const int b     = blockIdx.z & 3;
    const int t0    = blockIdx.x * 128;
    const int n0    = blockIdx.y * 128;
    const __half* X  = g_Xh + ((size_t)which * B_ + b) * T_ * E_ + (size_t)t0 * E_;
    const __half* Bm = g_Wth + (size_t)which * E_ * E_ + (size_t)n0 * E_;

    float C[2][8][4];
    gemm_tile_h(X, Bm, gsm, C);

    const int lane = threadIdx.x & 31, wid = threadIdx.x >> 5;
    const int ge = lane >> 2, te = lane & 3;
    const int mw = (wid & 3) * 32, nw = (wid >> 2) * 64;

#pragma unroll
    for (int i = 0; i < 2; i++) {
        const int t_lo = t0 + mw + 16 * i + ge;
#pragma unroll
        for (int j = 0; j < 8; j++) {
            const int c  = n0 + nw + 8 * j + 2 * te;
            const int h  = c >> 6, d = c & 63;
            const int bh = b * 16 + h;

            if (which == 0) {
                uint32_t w01 = packh2(C[i][j][0], C[i][j][1]);
                uint32_t w23 = packh2(C[i][j][2], C[i][j][3]);
                int qb = t_lo >> 7, tl = t_lo & 127;
                int rb = tl >> 4, gp = tl & 7;
                int ks = d >> 4, dk = d & 15;
                int tgp = (dk >> 1) & 3, rhi = (dk >> 3) << 1;
                size_t idx = ((size_t)bh * 16 + qb) * 4096 +
                             (size_t)(((ks * 8 + rb) * 32 + 4 * gp + tgp) * 4 + rhi);
                uint2 st; st.x = w01; st.y = w23;
                *(uint2*)&g_Qfh[idx] = st;
            } else if (which == 1) {
                uint32_t w01 = packh2(C[i][j][0], C[i][j][1]);
                uint32_t w23 = packh2(C[i][j][2], C[i][j][3]);
                int kt = t_lo >> 6, sidx = t_lo & 63;
                int jp = sidx >> 3, gp = sidx & 7;
                int ks = d >> 4, dk = d & 15;
                int reg = dk >> 3, tgp = (dk >> 1) & 3;
                size_t base = ((size_t)bh * 32 + kt) * 2048;
                g_Kfh[base + ((ks * 8 + jp) * 32 + 4 * gp + tgp) * 2 + reg] = w01;
                g_Kfh[base + ((ks * 8 + jp + 1) * 32 + 4 * gp + tgp) * 2 + reg] = w23;
            } else {
                float q0 = __shfl_xor_sync(0xffffffffu, C[i][j][0], 4);
                float q1 = __shfl_xor_sync(0xffffffffu, C[i][j][1], 4);
                float q2 = __shfl_xor_sync(0xffffffffu, C[i][j][2], 4);
                float q3 = __shfl_xor_sync(0xffffffffu, C[i][j][3], 4);
                if ((ge & 1) == 0) {
                    uint32_t wA = packh2(C[i][j][0], q0);
                    uint32_t wB = packh2(C[i][j][1], q1);
                    uint32_t wC = packh2(C[i][j][2], q2);
                    uint32_t wD = packh2(C[i][j][3], q3);
                    int kt = t_lo >> 6, sidx = t_lo & 63;
                    int ks = sidx >> 4, sk = sidx & 15;
                    int tgp = (sk >> 1) & 3;
                    int jp = d >> 3, gp = d & 7;
                    size_t base = ((size_t)bh * 32 + kt) * 2048;
                    size_t iA = base + ((ks * 8 + jp) * 32 + 4 * gp + tgp) * 2;
                    size_t iB = base + ((ks * 8 + jp) * 32 + 4 * (gp + 1) + tgp) * 2;
                    uint2 s0; s0.x = wA; s0.y = wC;
                    uint2 s1; s1.x = wB; s1.y = wD;
                    *(uint2*)&g_Vfh[iA] = s0;
                    *(uint2*)&g_Vfh[iB] = s1;
                }
            }
        }
    }
}

// ============================================================================
// Output projection: out = attn(fp16) @ Wp(fp16)^T + bp (fp32 epilogue).
// 256 threads.
// ============================================================================
__global__ __launch_bounds__(256, 2) void outproj_mma_kernel(
    const float* __restrict__ bp, float* __restrict__ out)
{
    extern __shared__ uint32_t gsm[];
    const int m0 = blockIdx.x * 128;
    const int n0 = blockIdx.y * 128;

    float C[2][8][4];
    gemm_tile_h(g_attnh + (size_t)m0 * E_, g_Wph + (size_t)n0 * E_, gsm, C);

    const int lane = threadIdx.x & 31, wid = threadIdx.x >> 5;
    const int g = lane >> 2, tg = lane & 3;
    const int mw = (wid & 3) * 32, nw = (wid >> 2) * 64;

#pragma unroll
    for (int i = 0; i < 2; i++) {
        size_t r = (size_t)(m0 + mw + 16 * i + g);
#pragma unroll
        for (int j = 0; j < 8; j++) {
            int cc = n0 + nw + 8 * j + 2 * tg;
            float2 bv = *(const float2*)&bp[cc];
            float2 v0 = {C[i][j][0] + bv.x, C[i][j][1] + bv.y};
            float2 v1 = {C[i][j][2] + bv.x, C[i][j][3] + bv.y};
            *(float2*)&out[r * E_ + cc] = v0;
            *(float2*)&out[(r + 8) * E_ + cc] = v1;
        }
    }
}

// ============================================================================
// Causal flash attention — R10/R14 structure, SINGLE change: launch_bounds
// (128, 3) to cap registers at 170 and fit 3 CTAs/SM (smem 3x64KB = 192KB).
// qf stays in registers. fp16 m16n8k16, log2-domain softmax, f16x2 MUFU exp;
// 128 threads, 4 warps x 32 rows; K,V triple-buffered; ONE barrier/iter;
// l via ones-column MMA. grid (T/128, B*H).
// ============================================================================
#define FQW 4096
#define FKW 2048
#define FLASH_SMEM_BYTES ((FQW + 3 * FKW + 3 * FKW) * 4)   // 65536
#define C2F 0.0450844331f   // log2(e) / 32
#define ONESH2 0x3C003C00u  // fp16x2 {1,1}

__global__ __launch_bounds__(128, 3) void flash_mma_kernel()
{
    extern __shared__ uint32_t smf[];
    uint32_t* Qs  = smf;
    uint32_t* Ks3 = smf + FQW;
    uint32_t* Vs3 = smf + FQW + 3 * FKW;

    const int bh = blockIdx.y;
    const int b  = bh >> 4, h = bh & 15;
    const int qb = gridDim.x - 1 - blockIdx.x;
    const int tid = threadIdx.x, w = tid >> 5, lane = tid & 31;
    const int g = lane >> 2, tg = lane & 3;
    const int last = 2 * qb + 1;

    const uint32_t* Qg = g_Qfh + ((size_t)bh * 16 + qb) * FQW;
    const uint32_t* Kg = g_Kfh + (size_t)bh * 32 * FKW;
    const uint32_t* Vg = g_Vfh + (size_t)bh * 32 * FKW;

    const uint32_t qs_u = smem_u32(Qs);
    const uint32_t ks_u = smem_u32(Ks3);
    const uint32_t vs_u = smem_u32(Vs3);

    auto issueKV = [&](int kt) {
        int st = kt % 3;
        const uint32_t kb = ks_u + (uint32_t)(st * FKW * 4);
        const uint32_t vb = vs_u + (uint32_t)(st * FKW * 4);
        const uint32_t* Kp = Kg + (size_t)kt * FKW;
        const uint32_t* Vp = Vg + (size_t)kt * FKW;
#pragma unroll
        for (int u = 0; u < 4; u++) {
            int idx = tid + (u << 7);
            cp16(kb + (uint32_t)idx * 16, Kp + (size_t)idx * 4);
            cp16(vb + (uint32_t)idx * 16, Vp + (size_t)idx * 4);
        }
        CP_COMMIT;
    };

    {
#pragma unroll
        for (int u = 0; u < 8; u++) {
            int idx = tid + (u << 7);
            cp16(qs_u + (uint32_t)idx * 16, Qg + (size_t)idx * 4);
        }
#pragma unroll
        for (int u = 0; u < 4; u++) {
            int idx = tid + (u << 7);
            cp16(ks_u + (uint32_t)idx * 16, Kg + (size_t)idx * 4);
            cp16(vs_u + (uint32_t)idx * 16, Vg + (size_t)idx * 4);
        }
        CP_COMMIT;
        if (last >= 1) issueKV(1);
    }

    uint32_t qf[2][4][4];
    float O[2][8][4];
    float Ol[2][4];                 // ones-column accumulators (l in [0],[2])
    float m_s[2][2];
#pragma unroll
    for (int i = 0; i < 2; i++) {
        m_s[i][0] = -INFINITY; m_s[i][1] = -INFINITY;
#pragma unroll
        for (int p = 0; p < 4; p++) Ol[i][p] = 0.f;
#pragma unroll
        for (int j = 0; j < 8; j++)
#pragma unroll
            for (int p = 0; p < 4; p++) O[i][j][p] = 0.f;
    }

    const int wr = qb * 128 + 32 * w;
    const uint32_t ones_bb[2] = {ONESH2, ONESH2};

    for (int kt = 0; kt <= last; kt++) {
        if (kt < last) { CP_WAIT1; } else { CP_WAIT0; }
        __syncthreads();
        if (kt + 2 <= last) issueKV(kt + 2);

        if (kt == 0) {
            const uint4* Qf4 = (const uint4*)Qs;
#pragma unroll
            for (int ks = 0; ks < 4; ks++)
#pragma unroll
                for (int i = 0; i < 2; i++) {
                    uint4 qa = Qf4[(ks * 8 + 2 * w + i) * 32 + lane];
                    qf[i][ks][0] = qa.x; qf[i][ks][1] = qa.y;
                    qf[i][ks][2] = qa.z; qf[i][ks][3] = qa.w;
                }
        }

        const int st = kt % 3;
        const uint2* Kf = (const uint2*)(Ks3 + (size_t)st * FKW);
        const uint2* Vf = (const uint2*)(Vs3 + (size_t)st * FKW);

        // ---- S = Q @ K^T (raw, unscaled) ----
        float S[2][8][4];
#pragma unroll
        for (int i = 0; i < 2; i++)
#pragma unroll
            for (int j = 0; j < 8; j++)
#pragma unroll
                for (int p = 0; p < 4; p++) S[i][j][p] = 0.f;

#pragma unroll
        for (int ks = 0; ks < 4; ks++)
#pragma unroll
            for (int j = 0; j < 8; j++) {
                uint2 kb = Kf[(ks * 8 + j) * 32 + lane];
                uint32_t bb[2] = {kb.x, kb.y};
                mma16h(S[0][j], qf[0][ks], bb);
                mma16h(S[1][j], qf[1][ks], bb);
            }

        // ---- causal mask (last two tiles only) ----
        if (kt >= 2 * qb) {
            const int kb0 = kt * 64;
#pragma unroll
            for (int i = 0; i < 2; i++) {
                int r0 = wr + 16 * i + g;
#pragma unroll
                for (int j = 0; j < 8; j++) {
                    int c0 = kb0 + 8 * j + 2 * tg;
                    if (c0 > r0)         S[i][j][0] = -INFINITY;
                    if (c0 + 1 > r0)     S[i][j][1] = -INFINITY;
                    if (c0 > r0 + 8)     S[i][j][2] = -INFINITY;
                    if (c0 + 1 > r0 + 8) S[i][j][3] = -INFINITY;
                }
            }
        }

        // ---- online softmax: exp via f16x2 MUFU, P lands as fp16x2 A-frags ----
        uint32_t Ph[2][8][2];
#pragma unroll
        for (int i = 0; i < 2; i++) {
            float rm0 = -INFINITY, rm1 = -INFINITY;
#pragma unroll
            for (int j = 0; j < 8; j++) {
                rm0 = fmaxf(rm0, fmaxf(S[i][j][0], S[i][j][1]));
                rm1 = fmaxf(rm1, fmaxf(S[i][j][2], S[i][j][3]));
            }
            rm0 = fmaxf(rm0, __shfl_xor_sync(0xffffffffu, rm0, 1));
            rm0 = fmaxf(rm0, __shfl_xor_sync(0xffffffffu, rm0, 2));
            rm1 = fmaxf(rm1, __shfl_xor_sync(0xffffffffu, rm1, 1));
            rm1 = fmaxf(rm1, __shfl_xor_sync(0xffffffffu, rm1, 2));

            float mn0 = fmaxf(m_s[i][0], rm0 * C2F);
            float mn1 = fmaxf(m_s[i][1], rm1 * C2F);
            float a0 = ex2f(m_s[i][0] - mn0), a1 = ex2f(m_s[i][1] - mn1);
#pragma unroll
            for (int j = 0; j < 8; j++) {
                float e0 = fmaf(S[i][j][0], C2F, -mn0);
                float e1 = fmaf(S[i][j][1], C2F, -mn0);
                float e2 = fmaf(S[i][j][2], C2F, -mn1);
                float e3 = fmaf(S[i][j][3], C2F, -mn1);
                Ph[i][j][0] = ex2h2(packh2(e0, e1));   // rows g   : P, fp16x2
                Ph[i][j][1] = ex2h2(packh2(e2, e3));   // rows g+8 : P, fp16x2
            }
            m_s[i][0] = mn0;
            m_s[i][1] = mn1;
#pragma unroll
            for (int j = 0; j < 8; j++) {
                O[i][j][0] *= a0; O[i][j][1] *= a0;
                O[i][j][2] *= a1; O[i][j][3] *= a1;
            }
            Ol[i][0] *= a0;
            Ol[i][2] *= a1;
        }

        // ---- O += P @ V (+ ones-column for l); A-frags = Ph directly ----
#pragma unroll
        for (int ks = 0; ks < 4; ks++) {
            uint32_t ap[2][4];
#pragma unroll
            for (int i = 0; i < 2; i++) {
                ap[i][0] = Ph[i][2 * ks][0];
                ap[i][1] = Ph[i][2 * ks][1];
                ap[i][2] = Ph[i][2 * ks + 1][0];
                ap[i][3] = Ph[i][2 * ks + 1][1];
            }
#pragma unroll
            for (int j = 0; j < 8; j++) {
                uint2 vb = Vf[(ks * 8 + j) * 32 + lane];
                uint32_t bb[2] = {vb.x, vb.y};
                mma16h(O[0][j], ap[0], bb);
                mma16h(O[1][j], ap[1], bb);
            }
            mma16h(Ol[0], ap[0], ones_bb);
            mma16h(Ol[1], ap[1], ones_bb);
        }
    }

    // ---- epilogue: normalize (l = Ol[i][0]/[2]), pack fp16, write [B,T,E] ----
#pragma unroll
    for (int i = 0; i < 2; i++) {
        float inv0 = 1.f / Ol[i][0], inv1 = 1.f / Ol[i][2];
        int row = wr + 16 * i + g;
        uint32_t* o0 = (uint32_t*)g_attnh + ((size_t)b * T_ + row) * (E_ / 2) + h * 32;
        uint32_t* o1 = o0 + 8 * (E_ / 2);
#pragma unroll
        for (int j = 0; j < 8; j++) {
            o0[4 * j + tg] = packh2(O[i][j][0] * inv0, O[i][j][1] * inv0);
            o1[4 * j + tg] = packh2(O[i][j][2] * inv1, O[i][j][3] * inv1);
        }
    }
}

// ============================================================================
extern "C" void kernel_launch(void* const* d_in, const int* in_sizes, int n_in,
                              void* d_out, int out_size)
{
    // metadata order: k, q, v, mask, Wk, Wq, Wv, Wp, bp
    const float* k  = (const float*)d_in[0];
    const float* q  = (const float*)d_in[1];
    const float* v  = (const float*)d_in[2];
    const float* Wk = (const float*)d_in[4];
    const float* Wq = (const float*)d_in[5];
    const float* Wv = (const float*)d_in[6];
    const float* Wp = (const float*)d_in[7];
    const float* bp = (const float*)d_in[8];
    float* out = (float*)d_out;

    cudaFuncSetAttribute(proj_mma_kernel,
                         cudaFuncAttributeMaxDynamicSharedMemorySize, GEMM_SMEM_BYTES);
    cudaFuncSetAttribute(outproj_mma_kernel,
                         cudaFuncAttributeMaxDynamicSharedMemorySize, GEMM_SMEM_BYTES);
    cudaFuncSetAttribute(flash_mma_kernel,
                         cudaFuncAttributeMaxDynamicSharedMemorySize, FLASH_SMEM_BYTES);

    prologue_kernel<<<dim3(8192, 5), 256>>>(q, k, v, Wp, Wq, Wk, Wv);

    proj_mma_kernel<<<dim3(T_ / 128, E_ / 128, 12), 256, GEMM_SMEM_BYTES>>>();

    flash_mma_kernel<<<dim3(T_ / 128, B_ * H_), 128, FLASH_SMEM_BYTES>>>();

    outproj_mma_kernel<<<dim3((B_ * T_) / 128, E_ / 128), 256, GEMM_SMEM_BYTES>>>(bp, out);
}

// round 16
// speedup vs baseline: 1.0623x; 1.0623x over previous
#include <cuda_runtime.h>
#include <cuda_fp16.h>
#include <math.h>
#include <stdint.h>

#define B_ 4
#define T_ 2048
#define E_ 1024
#define H_ 16

// Device-global scratch (allocation-free).
__device__ __half   g_Xh[(size_t)3 * B_ * T_ * E_];
__device__ __half   g_Wph[(size_t)E_ * E_];
__device__ __half   g_Wth[(size_t)3 * E_ * E_];
__device__ uint32_t g_Qfh[(size_t)64 * 16 * 4096];
__device__ uint32_t g_Kfh[(size_t)64 * 32 * 2048];
__device__ uint32_t g_Vfh[(size_t)64 * 32 * 2048];
__device__ __half   g_attnh[(size_t)B_ * T_ * E_];

// ============================================================================
// Helpers
// ============================================================================
__device__ __forceinline__ uint32_t packh2(float lo, float hi) {
    uint32_t r;
    asm("cvt.rn.f16x2.f32 %0, %1, %2;" : "=r"(r) : "f"(hi), "f"(lo));
    return r;
}

__device__ __forceinline__ float ex2f(float x) {
    float y;
    asm("ex2.approx.f32 %0, %1;" : "=f"(y) : "f"(x));
    return y;
}

// two fp16 exp2 in ONE MUFU op
__device__ __forceinline__ uint32_t ex2h2(uint32_t x) {
    uint32_t y;
    asm("ex2.approx.f16x2 %0, %1;" : "=r"(y) : "r"(x));
    return y;
}

__device__ __forceinline__ uint32_t smem_u32(const void* p) {
    uint32_t a;
    asm("{ .reg .u64 t; cvta.to.shared.u64 t, %1; cvt.u32.u64 %0, t; }"
        : "=r"(a) : "l"(p));
    return a;
}

// D(16x8,f32) += A(16x16,f16) * B(16x8,f16)
__device__ __forceinline__ void mma16h(float* c, const uint32_t* a, const uint32_t* b) {
    asm volatile(
        "mma.sync.aligned.m16n8k16.row.col.f32.f16.f16.f32 "
        "{%0,%1,%2,%3}, {%4,%5,%6,%7}, {%8,%9}, {%0,%1,%2,%3};"
        : "+f"(c[0]), "+f"(c[1]), "+f"(c[2]), "+f"(c[3])
        : "r"(a[0]), "r"(a[1]), "r"(a[2]), "r"(a[3]), "r"(b[0]), "r"(b[1]));
}

__device__ __forceinline__ void ldsm4(uint32_t* r, uint32_t a) {
    asm volatile("ldmatrix.sync.aligned.m8n8.x4.shared.b16 {%0,%1,%2,%3}, [%4];"
                 : "=r"(r[0]), "=r"(r[1]), "=r"(r[2]), "=r"(r[3]) : "r"(a));
}

__device__ __forceinline__ void cp16(uint32_t dst, const void* src) {
    asm volatile("cp.async.cg.shared.global [%0], [%1], 16;"
                 :: "r"(dst), "l"(src));
}
#define CP_COMMIT asm volatile("cp.async.commit_group;" ::: "memory")
#define CP_WAIT0  asm volatile("cp.async.wait_group 0;" ::: "memory")
#define CP_WAIT1  asm volatile("cp.async.wait_group 1;" ::: "memory")

// ============================================================================
// Merged prologue: z=0..3 -> g_Xh[z]=fp16(q|k|v), g_Wph=fp16(Wp);
//                  z=4    -> transpose all three W's into g_Wth.
// grid (8192, 5), 256 threads.
// ============================================================================
__global__ __launch_bounds__(256) void prologue_kernel(
    const float* __restrict__ q, const float* __restrict__ k,
    const float* __restrict__ v, const float* __restrict__ Wp,
    const float* __restrict__ Wq, const float* __restrict__ Wk,
    const float* __restrict__ Wv)
{
    const int z = blockIdx.y;
    const int tid = threadIdx.x;

    if (z < 4) {
        const float* src;
        __half* dst;
        size_t n4;
        if (z < 3) {
            src = (z == 0 ? q : (z == 1 ? k : v));
            dst = g_Xh + (size_t)z * B_ * T_ * E_;
            n4  = (size_t)B_ * T_ * E_ / 4;
        } else {
            src = Wp;
            dst = g_Wph;
            n4  = (size_t)E_ * E_ / 4;
        }
        size_t i = (size_t)blockIdx.x * 256 + tid;
        if (i < n4) {
            float4 x = ((const float4*)src)[i];
            uint2 o;
            o.x = packh2(x.x, x.y);
            o.y = packh2(x.z, x.w);
            ((uint2*)dst)[i] = o;
        }
        return;
    }

    // z == 4: weight transpose. 768 active blocks.
    if (blockIdx.x >= 768) return;
    __shared__ float tile[64][65];
    const int which = blockIdx.x >> 8;          // 0..2
    const int rem   = blockIdx.x & 255;
    const int h     = rem >> 4;                 // 0..15
    const int e0    = (rem & 15) * 64;
    const float* W = (which == 0 ? Wq : (which == 1 ? Wk : Wv)) + (size_t)h * E_ * 64;

#pragma unroll
    for (int u = 0; u < 16; u++) {
        int idx = tid + u * 256;
        int r = idx >> 6, c = idx & 63;
        tile[r][c] = W[(size_t)(e0 + r) * 64 + c];
    }
    __syncthreads();

    __half* out = g_Wth + (size_t)which * E_ * E_;
#pragma unroll
    for (int u = 0; u < 16; u++) {
        int idx = tid + u * 256;
        int d = idx >> 6, ee = idx & 63;
        out[(size_t)(h * 64 + d) * E_ + e0 + ee] = __float2half_rn(tile[ee][d]);
    }
}

// ============================================================================
// fp16 GEMM core (cp.async 3-stage, ldmatrix, BK=64) — R10 config:
// C[128,128] = A[128,K=1024] @ B[128,K=1024]^T, 16 chunks of 64 (4 k16 steps).
// 256 threads / 8 warps (4M x 2N), warp tile 32x64. smem row 72 halves
// (stride-36 words: 8 rows x stride-36 -> phases 4r mod 32 distinct, LDSM cf).
// ============================================================================
#define HLD 36
#define GSW (128 * HLD)
#define GEMM_SMEM_BYTES (6 * GSW * 4)        // 110592

__device__ __forceinline__ void gemm_issue_h(
    const __half* __restrict__ A, const __half* __restrict__ Bm,
    uint32_t su, int c, int s, int tid)
{
    const __half* Ac = A + (c << 6);
    const __half* Bc = Bm + (c << 6);
    const uint32_t ab = su + (uint32_t)s * GSW * 4;
    const uint32_t bb = su + (uint32_t)(3 + s) * GSW * 4;
#pragma unroll
    for (int u = 0; u < 4; u++) {
        int idx = tid + (u << 8);           // 0..1023
        int r = idx >> 3, qq = idx & 7;
        uint32_t so = (uint32_t)r * 144 + (uint32_t)qq * 16;
        cp16(ab + so, Ac + (size_t)r * E_ + (qq << 3));
        cp16(bb + so, Bc + (size_t)r * E_ + (qq << 3));
    }
    CP_COMMIT;
}

__device__ __forceinline__ void gemm_tile_h(
    const __half* __restrict__ A, const __half* __restrict__ Bm,
    uint32_t* smw, float C[2][8][4])
{
    const int tid = threadIdx.x, wid = tid >> 5, lane = tid & 31;
    const int mw = (wid & 3) * 32, nw = (wid >> 2) * 64;
    const int i0 = lane & 7, sel = lane >> 3;
    const uint32_t su = smem_u32(smw);

    const int arow = (mw + i0 + ((sel & 1) << 3)) * HLD + ((sel >> 1) << 2);
    int brow[4];
#pragma unroll
    for (int p = 0; p < 4; p++)
        brow[p] = (nw + 16 * p + ((sel >> 1) << 3) + i0) * HLD + ((sel & 1) << 2);

#pragma unroll
    for (int i = 0; i < 2; i++)
#pragma unroll
        for (int j = 0; j < 8; j++)
#pragma unroll
            for (int p = 0; p < 4; p++) C[i][j][p] = 0.f;

    gemm_issue_h(A, Bm, su, 0, 0, tid);
    gemm_issue_h(A, Bm, su, 1, 1, tid);

    int s = 0;
    for (int c = 0; c < 16; c++) {
        if (c < 15) { CP_WAIT1; } else { CP_WAIT0; }
        __syncthreads();
        if (c + 2 < 16) {
            int sn = s + 2; if (sn >= 3) sn -= 3;
            gemm_issue_h(A, Bm, su, c + 2, sn, tid);
        }
        const uint32_t aBase = su + (uint32_t)s * (GSW * 4);
        const uint32_t bBase = su + (uint32_t)(3 + s) * (GSW * 4);
#pragma unroll
        for (int ks = 0; ks < 4; ks++) {
            const int ko = ks * 8;
            uint32_t af[2][4], bf[4][4];
            ldsm4(af[0], aBase + (uint32_t)(arow + ko) * 4);
            ldsm4(af[1], aBase + (uint32_t)(arow + 16 * HLD + ko) * 4);
#pragma unroll
            for (int p = 0; p < 4; p++)
                ldsm4(bf[p], bBase + (uint32_t)(brow[p] + ko) * 4);
#pragma unroll
            for (int i = 0; i < 2; i++)
#pragma unroll
                for (int p = 0; p < 4; p++) {
                    mma16h(C[i][2 * p],     af[i], &bf[p][0]);
                    mma16h(C[i][2 * p + 1], af[i], &bf[p][2]);
                }
        }
        if (++s == 3) s = 0;
    }
}

// ============================================================================
// QKV projection: grid (T/128, E/128, 12 = which*4+b). 256 threads.
// Epilogue packs fp16x2 and scatters into fragment blobs. Q stays UNscaled.
// ============================================================================
__global__ __launch_bounds__(256, 2) void proj_mma_kernel()
{
    extern __shared__ uint32_t gsm[];
    const int which = blockIdx.z >> 2;
    const int b     = blockIdx.z & 3;
    const int t0    = blockIdx.x * 128;
    const int n0    = blockIdx.y * 128;
    const __half* X  = g_Xh + ((size_t)which * B_ + b) * T_ * E_ + (size_t)t0 * E_;
    const __half* Bm = g_Wth + (size_t)which * E_ * E_ + (size_t)n0 * E_;

    float C[2][8][4];
    gemm_tile_h(X, Bm, gsm, C);

    const int lane = threadIdx.x & 31, wid = threadIdx.x >> 5;
    const int ge = lane >> 2, te = lane & 3;
    const int mw = (wid & 3) * 32, nw = (wid >> 2) * 64;

#pragma unroll
    for (int i = 0; i < 2; i++) {
        const int t_lo = t0 + mw + 16 * i + ge;
#pragma unroll
        for (int j = 0; j < 8; j++) {
            const int c  = n0 + nw + 8 * j + 2 * te;
            const int h  = c >> 6, d = c & 63;
            const int bh = b * 16 + h;

            if (which == 0) {
                uint32_t w01 = packh2(C[i][j][0], C[i][j][1]);
                uint32_t w23 = packh2(C[i][j][2], C[i][j][3]);
                int qb = t_lo >> 7, tl = t_lo & 127;
                int rb = tl >> 4, gp = tl & 7;
                int ks = d >> 4, dk = d & 15;
                int tgp = (dk >> 1) & 3, rhi = (dk >> 3) << 1;
                size_t idx = ((size_t)bh * 16 + qb) * 4096 +
                             (size_t)(((ks * 8 + rb) * 32 + 4 * gp + tgp) * 4 + rhi);
                uint2 st; st.x = w01; st.y = w23;
                *(uint2*)&g_Qfh[idx] = st;
            } else if (which == 1) {
                uint32_t w01 = packh2(C[i][j][0], C[i][j][1]);
                uint32_t w23 = packh2(C[i][j][2], C[i][j][3]);
                int kt = t_lo >> 6, sidx = t_lo & 63;
                int jp = sidx >> 3, gp = sidx & 7;
                int ks = d >> 4, dk = d & 15;
                int reg = dk >> 3, tgp = (dk >> 1) & 3;
                size_t base = ((size_t)bh * 32 + kt) * 2048;
                g_Kfh[base + ((ks * 8 + jp) * 32 + 4 * gp + tgp) * 2 + reg] = w01;
                g_Kfh[base + ((ks * 8 + jp + 1) * 32 + 4 * gp + tgp) * 2 + reg] = w23;
            } else {
                float q0 = __shfl_xor_sync(0xffffffffu, C[i][j][0], 4);
                float q1 = __shfl_xor_sync(0xffffffffu, C[i][j][1], 4);
                float q2 = __shfl_xor_sync(0xffffffffu, C[i][j][2], 4);
                float q3 = __shfl_xor_sync(0xffffffffu, C[i][j][3], 4);
                if ((ge & 1) == 0) {
                    uint32_t wA = packh2(C[i][j][0], q0);
                    uint32_t wB = packh2(C[i][j][1], q1);
                    uint32_t wC = packh2(C[i][j][2], q2);
                    uint32_t wD = packh2(C[i][j][3], q3);
                    int kt = t_lo >> 6, sidx = t_lo & 63;
                    int ks = sidx >> 4, sk = sidx & 15;
                    int tgp = (sk >> 1) & 3;
                    int jp = d >> 3, gp = d & 7;
                    size_t base = ((size_t)bh * 32 + kt) * 2048;
                    size_t iA = base + ((ks * 8 + jp) * 32 + 4 * gp + tgp) * 2;
                    size_t iB = base + ((ks * 8 + jp) * 32 + 4 * (gp + 1) + tgp) * 2;
                    uint2 s0; s0.x = wA; s0.y = wC;
                    uint2 s1; s1.x = wB; s1.y = wD;
                    *(uint2*)&g_Vfh[iA] = s0;
                    *(uint2*)&g_Vfh[iB] = s1;
                }
            }
        }
    }
}

// ============================================================================
// Output projection: out = attn(fp16) @ Wp(fp16)^T + bp (fp32 epilogue).
// 256 threads.
// ============================================================================
__global__ __launch_bounds__(256, 2) void outproj_mma_kernel(
    const float* __restrict__ bp, float* __restrict__ out)
{
    extern __shared__ uint32_t gsm[];
    const int m0 = blockIdx.x * 128;
    const int n0 = blockIdx.y * 128;

    float C[2][8][4];
    gemm_tile_h(g_attnh + (size_t)m0 * E_, g_Wph + (size_t)n0 * E_, gsm, C);

    const int lane = threadIdx.x & 31, wid = threadIdx.x >> 5;
    const int g = lane >> 2, tg = lane & 3;
    const int mw = (wid & 3) * 32, nw = (wid >> 2) * 64;

#pragma unroll
    for (int i = 0; i < 2; i++) {
        size_t r = (size_t)(m0 + mw + 16 * i + g);
#pragma unroll
        for (int j = 0; j < 8; j++) {
            int cc = n0 + nw + 8 * j + 2 * tg;
            float2 bv = *(const float2*)&bp[cc];
            float2 v0 = {C[i][j][0] + bv.x, C[i][j][1] + bv.y};
            float2 v1 = {C[i][j][2] + bv.x, C[i][j][3] + bv.y};
            *(float2*)&out[r * E_ + cc] = v0;
            *(float2*)&out[(r + 8) * E_ + cc] = v1;
        }
    }
}

// ============================================================================
// Causal flash attention — EXACT R14 configuration (global best: 363.2us).
// fp16 m16n8k16, log2-domain softmax, f16x2 MUFU exp; 128 threads, 4 warps
// x 32 rows; Q frags held in registers; K,V triple-buffered; ONE barrier per
// iteration; l via ones-column MMA; (128,2). grid (T/128, B*H).
// ============================================================================
#define FQW 4096
#define FKW 2048
#define FLASH_SMEM_BYTES ((FQW + 3 * FKW + 3 * FKW) * 4)   // 65536
#define C2F 0.0450844331f   // log2(e) / 32
#define ONESH2 0x3C003C00u  // fp16x2 {1,1}

__global__ __launch_bounds__(128, 2) void flash_mma_kernel()
{
    extern __shared__ uint32_t smf[];
    uint32_t* Qs  = smf;
    uint32_t* Ks3 = smf + FQW;
    uint32_t* Vs3 = smf + FQW + 3 * FKW;

    const int bh = blockIdx.y;
    const int b  = bh >> 4, h = bh & 15;
    const int qb = gridDim.x - 1 - blockIdx.x;
    const int tid = threadIdx.x, w = tid >> 5, lane = tid & 31;
    const int g = lane >> 2, tg = lane & 3;
    const int last = 2 * qb + 1;

    const uint32_t* Qg = g_Qfh + ((size_t)bh * 16 + qb) * FQW;
    const uint32_t* Kg = g_Kfh + (size_t)bh * 32 * FKW;
    const uint32_t* Vg = g_Vfh + (size_t)bh * 32 * FKW;

    const uint32_t qs_u = smem_u32(Qs);
    const uint32_t ks_u = smem_u32(Ks3);
    const uint32_t vs_u = smem_u32(Vs3);

    auto issueKV = [&](int kt) {
        int st = kt % 3;
        const uint32_t kb = ks_u + (uint32_t)(st * FKW * 4);
        const uint32_t vb = vs_u + (uint32_t)(st * FKW * 4);
        const uint32_t* Kp = Kg + (size_t)kt * FKW;
        const uint32_t* Vp = Vg + (size_t)kt * FKW;
#pragma unroll
        for (int u = 0; u < 4; u++) {
            int idx = tid + (u << 7);
            cp16(kb + (uint32_t)idx * 16, Kp + (size_t)idx * 4);
            cp16(vb + (uint32_t)idx * 16, Vp + (size_t)idx * 4);
        }
        CP_COMMIT;
    };

    {
#pragma unroll
        for (int u = 0; u < 8; u++) {
            int idx = tid + (u << 7);
            cp16(qs_u + (uint32_t)idx * 16, Qg + (size_t)idx * 4);
        }
#pragma unroll
        for (int u = 0; u < 4; u++) {
            int idx = tid + (u << 7);
            cp16(ks_u + (uint32_t)idx * 16, Kg + (size_t)idx * 4);
            cp16(vs_u + (uint32_t)idx * 16, Vg + (size_t)idx * 4);
        }
        CP_COMMIT;
        if (last >= 1) issueKV(1);
    }

    uint32_t qf[2][4][4];
    float O[2][8][4];
    float Ol[2][4];                 // ones-column accumulators (l in [0],[2])
    float m_s[2][2];
#pragma unroll
    for (int i = 0; i < 2; i++) {
        m_s[i][0] = -INFINITY; m_s[i][1] = -INFINITY;
#pragma unroll
        for (int p = 0; p < 4; p++) Ol[i][p] = 0.f;
#pragma unroll
        for (int j = 0; j < 8; j++)
#pragma unroll
            for (int p = 0; p < 4; p++) O[i][j][p] = 0.f;
    }

    const int wr = qb * 128 + 32 * w;
    const uint32_t ones_bb[2] = {ONESH2, ONESH2};

    for (int kt = 0; kt <= last; kt++) {
        if (kt < last) { CP_WAIT1; } else { CP_WAIT0; }
        __syncthreads();
        if (kt + 2 <= last) issueKV(kt + 2);

        if (kt == 0) {
            const uint4* Qf4 = (const uint4*)Qs;
#pragma unroll
            for (int ks = 0; ks < 4; ks++)
#pragma unroll
                for (int i = 0; i < 2; i++) {
                    uint4 qa = Qf4[(ks * 8 + 2 * w + i) * 32 + lane];
                    qf[i][ks][0] = qa.x; qf[i][ks][1] = qa.y;
                    qf[i][ks][2] = qa.z; qf[i][ks][3] = qa.w;
                }
        }

        const int st = kt % 3;
        const uint2* Kf = (const uint2*)(Ks3 + (size_t)st * FKW);
        const uint2* Vf = (const uint2*)(Vs3 + (size_t)st * FKW);

        // ---- S = Q @ K^T (raw, unscaled) ----
        float S[2][8][4];
#pragma unroll
        for (int i = 0; i < 2; i++)
#pragma unroll
            for (int j = 0; j < 8; j++)
#pragma unroll
                for (int p = 0; p < 4; p++) S[i][j][p] = 0.f;

#pragma unroll
        for (int ks = 0; ks < 4; ks++)
#pragma unroll
            for (int j = 0; j < 8; j++) {
                uint2 kb = Kf[(ks * 8 + j) * 32 + lane];
                uint32_t bb[2] = {kb.x, kb.y};
                mma16h(S[0][j], qf[0][ks], bb);
                mma16h(S[1][j], qf[1][ks], bb);
            }

        // ---- causal mask (last two tiles only) ----
        if (kt >= 2 * qb) {
            const int kb0 = kt * 64;
#pragma unroll
            for (int i = 0; i < 2; i++) {
                int r0 = wr + 16 * i + g;
#pragma unroll
                for (int j = 0; j < 8; j++) {
                    int c0 = kb0 + 8 * j + 2 * tg;
                    if (c0 > r0)         S[i][j][0] = -INFINITY;
                    if (c0 + 1 > r0)     S[i][j][1] = -INFINITY;
                    if (c0 > r0 + 8)     S[i][j][2] = -INFINITY;
                    if (c0 + 1 > r0 + 8) S[i][j][3] = -INFINITY;
                }
            }
        }

        // ---- online softmax: exp via f16x2 MUFU, P lands as fp16x2 A-frags ----
        uint32_t Ph[2][8][2];
#pragma unroll
        for (int i = 0; i < 2; i++) {
            float rm0 = -INFINITY, rm1 = -INFINITY;
#pragma unroll
            for (int j = 0; j < 8; j++) {
                rm0 = fmaxf(rm0, fmaxf(S[i][j][0], S[i][j][1]));
                rm1 = fmaxf(rm1, fmaxf(S[i][j][2], S[i][j][3]));
            }
            rm0 = fmaxf(rm0, __shfl_xor_sync(0xffffffffu, rm0, 1));
            rm0 = fmaxf(rm0, __shfl_xor_sync(0xffffffffu, rm0, 2));
            rm1 = fmaxf(rm1, __shfl_xor_sync(0xffffffffu, rm1, 1));
            rm1 = fmaxf(rm1, __shfl_xor_sync(0xffffffffu, rm1, 2));

            float mn0 = fmaxf(m_s[i][0], rm0 * C2F);
            float mn1 = fmaxf(m_s[i][1], rm1 * C2F);
            float a0 = ex2f(m_s[i][0] - mn0), a1 = ex2f(m_s[i][1] - mn1);
#pragma unroll
            for (int j = 0; j < 8; j++) {
                float e0 = fmaf(S[i][j][0], C2F, -mn0);
                float e1 = fmaf(S[i][j][1], C2F, -mn0);
                float e2 = fmaf(S[i][j][2], C2F, -mn1);
                float e3 = fmaf(S[i][j][3], C2F, -mn1);
                Ph[i][j][0] = ex2h2(packh2(e0, e1));   // rows g   : P, fp16x2
                Ph[i][j][1] = ex2h2(packh2(e2, e3));   // rows g+8 : P, fp16x2
            }
            m_s[i][0] = mn0;
            m_s[i][1] = mn1;
#pragma unroll
            for (int j = 0; j < 8; j++) {
                O[i][j][0] *= a0; O[i][j][1] *= a0;
                O[i][j][2] *= a1; O[i][j][3] *= a1;
            }
            Ol[i][0] *= a0;
            Ol[i][2] *= a1;
        }

        // ---- O += P @ V (+ ones-column for l); A-frags = Ph directly ----
#pragma unroll
        for (int ks = 0; ks < 4; ks++) {
            uint32_t ap[2][4];
#pragma unroll
            for (int i = 0; i < 2; i++) {
                ap[i][0] = Ph[i][2 * ks][0];
                ap[i][1] = Ph[i][2 * ks][1];
                ap[i][2] = Ph[i][2 * ks + 1][0];
                ap[i][3] = Ph[i][2 * ks + 1][1];
            }
#pragma unroll
            for (int j = 0; j < 8; j++) {
                uint2 vb = Vf[(ks * 8 + j) * 32 + lane];
                uint32_t bb[2] = {vb.x, vb.y};
                mma16h(O[0][j], ap[0], bb);
                mma16h(O[1][j], ap[1], bb);
            }
            mma16h(Ol[0], ap[0], ones_bb);
            mma16h(Ol[1], ap[1], ones_bb);
        }
    }

    // ---- epilogue: normalize (l = Ol[i][0]/[2]), pack fp16, write [B,T,E] ----
#pragma unroll
    for (int i = 0; i < 2; i++) {
        float inv0 = 1.f / Ol[i][0], inv1 = 1.f / Ol[i][2];
        int row = wr + 16 * i + g;
        uint32_t* o0 = (uint32_t*)g_attnh + ((size_t)b * T_ + row) * (E_ / 2) + h * 32;
        uint32_t* o1 = o0 + 8 * (E_ / 2);
#pragma unroll
        for (int j = 0; j < 8; j++) {
            o0[4 * j + tg] = packh2(O[i][j][0] * inv0, O[i][j][1] * inv0);
            o1[4 * j + tg] = packh2(O[i][j][2] * inv1, O[i][j][3] * inv1);
        }
    }
}

// ============================================================================
extern "C" void kernel_launch(void* const* d_in, const int* in_sizes, int n_in,
                              void* d_out, int out_size)
{
    // metadata order: k, q, v, mask, Wk, Wq, Wv, Wp, bp
    const float* k  = (const float*)d_in[0];
    const float* q  = (const float*)d_in[1];
    const float* v  = (const float*)d_in[2];
    const float* Wk = (const float*)d_in[4];
    const float* Wq = (const float*)d_in[5];
    const float* Wv = (const float*)d_in[6];
    const float* Wp = (const float*)d_in[7];
    const float* bp = (const float*)d_in[8];
    float* out = (float*)d_out;

    cudaFuncSetAttribute(proj_mma_kernel,
                         cudaFuncAttributeMaxDynamicSharedMemorySize, GEMM_SMEM_BYTES);
    cudaFuncSetAttribute(outproj_mma_kernel,
                         cudaFuncAttributeMaxDynamicSharedMemorySize, GEMM_SMEM_BYTES);
    cudaFuncSetAttribute(flash_mma_kernel,
                         cudaFuncAttributeMaxDynamicSharedMemorySize, FLASH_SMEM_BYTES);

    prologue_kernel<<<dim3(8192, 5), 256>>>(q, k, v, Wp, Wq, Wk, Wv);

    proj_mma_kernel<<<dim3(T_ / 128, E_ / 128, 12), 256, GEMM_SMEM_BYTES>>>();

    flash_mma_kernel<<<dim3(T_ / 128, B_ * H_), 128, FLASH_SMEM_BYTES>>>();

    outproj_mma_kernel<<<dim3((B_ * T_) / 128, E_ / 128), 256, GEMM_SMEM_BYTES>>>(bp, out);
}